// round 13
// baseline (speedup 1.0000x reference)
#include <cuda_runtime.h>
#include <cstdint>

// Problem constants
#define A_BATCH 128
#define M_LEN   256
#define D_DIM   16
#define MM      255            // PDE grid size (M-1)
#define NTASK   384            // 3 PDE solves x 128 batch

// Ring geometry: one slot per column of (c1,c2) pairs.
// Lane region = 20 words (16 data + 4 pad): conflict-free LDS.128/STS.128.
// RB=38 -> producer gate cons >= c-7; publish cadence every 3 steps keeps
// all wait margins >= 0 (no deadlock).
#define RB      38
#define SLOT_W  640            // 20 words * 32 lanes
#define SLOT_B  (SLOT_W * 4)   // 2560 bytes
#define RING_W  (RB * SLOT_W)  // 24320 words
#define DY_W    (MM * D_DIM)   // 4080 words
#define FLAGS_OFF (RING_W + DY_W)
#define TEAM_W  (FLAGS_OFF + 8)
#define SMEM_BYTES (TEAM_W * 4)   // 113,632 B -> 2 CTAs/SM co-resident

typedef unsigned long long u64;
typedef unsigned int u32;

__device__ float g_partial[NTASK];
__device__ int   g_done = 0;       // last-CTA counter (reset by the last CTA)

__device__ __forceinline__ u64 pack2(float lo, float hi) {
    u64 r; asm("mov.b64 %0,{%1,%2};" : "=l"(r) : "f"(lo), "f"(hi)); return r;
}
__device__ __forceinline__ void unpack2(u64 v, float& lo, float& hi) {
    asm("mov.b64 {%0,%1},%2;" : "=f"(lo), "=f"(hi) : "l"(v));
}
__device__ __forceinline__ u64 fma2(u64 a, u64 b, u64 c) {
    u64 d; asm("fma.rn.f32x2 %0,%1,%2,%3;" : "=l"(d) : "l"(a), "l"(b), "l"(c)); return d;
}
__device__ __forceinline__ u64 mul2(u64 a, u64 b) {
    u64 d; asm("mul.rn.f32x2 %0,%1,%2;" : "=l"(d) : "l"(a), "l"(b)); return d;
}
__device__ __forceinline__ int lds_acq(u32 a) {
    int v; asm volatile("ld.acquire.cta.shared.b32 %0,[%1];" : "=r"(v) : "r"(a)); return v;
}
__device__ __forceinline__ void sts_rel(u32 a, int v) {
    asm volatile("st.release.cta.shared.b32 [%0],%1;" :: "r"(a), "r"(v));
}
__device__ __forceinline__ void lds128(u32 a, float& x, float& y, float& z, float& w) {
    asm volatile("ld.shared.v4.f32 {%0,%1,%2,%3},[%4];"
                 : "=f"(x), "=f"(y), "=f"(z), "=f"(w) : "r"(a));
}
__device__ __forceinline__ void sts128(u32 a, float x, float y, float z, float w) {
    asm volatile("st.shared.v4.f32 [%0],{%1,%2,%3,%4};"
                 :: "r"(a), "f"(x), "f"(y), "f"(z), "f"(w));
}

// One CTA = one task = 128 threads. Consumer = warp 3; producers = warps
// 0..2 (warp p owns columns ≡ p mod 3; lane computes rows 8l..8l+7 from
// register dX). Monotonic flags, acquire/release. Steady-state consumer has
// ONE combined (usually-skipped) flag check per 3 steps and branch-free
// all-lane publishes — no per-step divergent control flow.
__global__ void __launch_bounds__(128, 2) sig_pde_kernel(
    const float* __restrict__ X, const float* __restrict__ Y,
    float* __restrict__ out)
{
    extern __shared__ float smem[];
    u32 sb;
    asm("{.reg .u64 t; cvta.to.shared.u64 t,%1; cvt.u32.u64 %0,t;}"
        : "=r"(sb) : "l"(smem));

    const int t    = threadIdx.x;
    const int q    = t >> 5;           // warp 0..3
    const int lane = t & 31;

    const int task = (int)blockIdx.x;
    const int pde  = task >> 7;        // 0:(X,X) 1:(Y,Y) 2:(X,Y)
    const int a    = task & 127;
    const float* rowsrc = (pde == 1 ? Y : X) + (size_t)a * (M_LEN * D_DIM);
    const float* colsrc = (pde == 0 ? X : Y) + (size_t)a * (M_LEN * D_DIM);

    float* s_dY = smem + RING_W;
    const u32 ring_b  = sb;
    const u32 flags_b = sb + FLAGS_OFF * 4;

    // dY[j][k] = colsrc[j+1][k] - colsrc[j][k]
    for (int idx = t; idx < DY_W; idx += 128)
        s_dY[idx] = colsrc[idx + D_DIM] - colsrc[idx];
    if (t < 4) ((volatile int*)(smem + FLAGS_OFF))[t] = -1; // done0..2, cons
    __syncthreads();   // the ONLY cta barrier

    if (q == 3) {
        // ======================= CONSUMER (warp 3) =======================
        float L[8];
#pragma unroll
        for (int r = 0; r < 8; r++) L[r] = 1.0f;     // K[row+1][0] = 1
        float nb_prev = 1.0f, last = 0.0f;
        u32 ad = ring_b + 80u * (u32)lane;
        const u32 ad_lim = ad + (u32)(RB * SLOT_B);
        const u32 cons_a = flags_b + 12;
        const u32 fa0 = flags_b, fa1 = flags_b + 4, fa2 = flags_b + 8;
        int f0 = -1, f1 = -1, f2 = -1;

        auto waitf = [&](int& f, u32 fa, int s) {
            if (f < s) { do { f = lds_acq(fa); } while (f < s); }
        };
        // combined wait: streams 1,2,0 must reach cols a1,a2,a0
        auto wait3 = [&](int a1, int a2, int a0) {
            if (f1 < a1 || f2 < a2 || f0 < a0) {
                do {
                    f0 = lds_acq(fa0); f1 = lds_acq(fa1); f2 = lds_acq(fa2);
                } while (f1 < a1 || f2 < a2 || f0 < a0);
            }
        };
        auto loadR = [&](float* R) {                 // load col at ad, advance
            lds128(ad,      R[0],  R[1],  R[2],  R[3]);
            lds128(ad + 16, R[4],  R[5],  R[6],  R[7]);
            lds128(ad + 32, R[8],  R[9],  R[10], R[11]);
            lds128(ad + 48, R[12], R[13], R[14], R[15]);
            ad += SLOT_B;
            if (ad >= ad_lim) ad -= (u32)(RB * SLOT_B);
        };
        auto chain = [&](const float* R, float nb_new) {
            const float up0 = (lane == 0) ? 1.0f : nb_new;
            const float dg0 = (lane == 0) ? 1.0f : nb_prev;
            float P0 = fmaf(L[0], R[0],  -(dg0  * R[1]));
            float P1 = fmaf(L[1], R[2],  -(L[0] * R[3]));
            float P2 = fmaf(L[2], R[4],  -(L[1] * R[5]));
            float P3 = fmaf(L[3], R[6],  -(L[2] * R[7]));
            float P4 = fmaf(L[4], R[8],  -(L[3] * R[9]));
            float P5 = fmaf(L[5], R[10], -(L[4] * R[11]));
            float P6 = fmaf(L[6], R[12], -(L[5] * R[13]));
            float P7 = fmaf(L[7], R[14], -(L[6] * R[15]));
            float k = fmaf(up0, R[0], P0); L[0] = k;
            k = fmaf(k, R[2],  P1); L[1] = k;
            k = fmaf(k, R[4],  P2); L[2] = k;
            k = fmaf(k, R[6],  P3); L[3] = k;
            k = fmaf(k, R[8],  P4); L[4] = k;
            k = fmaf(k, R[10], P5); L[5] = k;
            k = fmaf(k, R[12], P6); L[6] = k;
            k = fmaf(k, R[14], P7); L[7] = k;
            last = k;
            nb_prev = nb_new;
        };
        auto body_ld = [&](float nb_new) {           // direct load + chain
            float R[16];
            loadR(R);
            chain(R, nb_new);
        };

        // ---- ramp: s = 0..32 (lane predicates + cached per-step waits) ----
#pragma unroll 1
        for (int s = 0; s < 33; s += 3) {
            { float nb = __shfl_up_sync(0xffffffffu, last, 1);
              waitf(f0, fa0, s);     if (lane <= s)     body_ld(nb); }
            { float nb = __shfl_up_sync(0xffffffffu, last, 1);
              waitf(f1, fa1, s + 1); if (lane <= s + 1) body_ld(nb); }
            { float nb = __shfl_up_sync(0xffffffffu, last, 1);
              waitf(f2, fa2, s + 2); if (lane <= s + 2) body_ld(nb); }
            sts_rel(cons_a, s + 2);                  // branchless publish
        }

        // ---- steady (pipelined): steps 33..248 in 6-step groups ----
        // Invariant at group head: R holds (per-lane) the column of step s.
        float R[16], T[16];
        waitf(f0, fa0, 33);
        loadR(R);                                    // data for step 33
#pragma unroll 1
        for (int s = 33; s <= 243; s += 6) {
            wait3(s + 1, s + 2, s + 3);              // cols s+1..s+3
            { float nb = __shfl_up_sync(0xffffffffu, last, 1);
              loadR(T); chain(R, nb); }              // s
            { float nb = __shfl_up_sync(0xffffffffu, last, 1);
              loadR(R); chain(T, nb); }              // s+1
            { float nb = __shfl_up_sync(0xffffffffu, last, 1);
              loadR(T); chain(R, nb); }              // s+2
            sts_rel(cons_a, s + 2);
            wait3(s + 4, s + 5, s + 6);              // cols s+4..s+6
            { float nb = __shfl_up_sync(0xffffffffu, last, 1);
              loadR(R); chain(T, nb); }              // s+3
            { float nb = __shfl_up_sync(0xffffffffu, last, 1);
              loadR(T); chain(R, nb); }              // s+4
            { float nb = __shfl_up_sync(0xffffffffu, last, 1);
              loadR(R); chain(T, nb); }              // s+5
            sts_rel(cons_a, s + 5);
        }
        // ---- peel: steps 249..254; one wait for the final columns ----
        wait3(253, 254, 252);                        // f1>=253, f2>=254, f0>=252
        { float nb = __shfl_up_sync(0xffffffffu, last, 1);
          loadR(T); chain(R, nb); }                  // 249 (load 250)
        { float nb = __shfl_up_sync(0xffffffffu, last, 1);
          loadR(R); chain(T, nb); }                  // 250 (load 251)
        { float nb = __shfl_up_sync(0xffffffffu, last, 1);
          loadR(T); chain(R, nb); }                  // 251 (load 252)
        { float nb = __shfl_up_sync(0xffffffffu, last, 1);
          loadR(R); chain(T, nb); }                  // 252 (load 253)
        { float nb = __shfl_up_sync(0xffffffffu, last, 1);
          loadR(T); chain(R, nb); }                  // 253 (load 254)
        { float nb = __shfl_up_sync(0xffffffffu, last, 1);
          chain(T, nb); }                            // 254 (no load)

        // ---- tail: s = 255..285, flag-free ----
#pragma unroll 1
        for (int s = 255; s < 286; s++) {
            float nb = __shfl_up_sync(0xffffffffu, last, 1);
            if (lane >= s - 254) body_ld(nb);
        }
        // K[255][255] = L[6] of lane 31 (global row 254)
        if (lane == 31) g_partial[task] = L[6];

        // ---- fused reduction: last CTA sums all partials ----
        int old = 0;
        if (lane == 31) {
            __threadfence();                         // g_partial visible
            old = atomicAdd(&g_done, 1);
        }
        old = __shfl_sync(0xffffffffu, old, 31);
        if (old == NTASK - 1) {
            __threadfence();                         // see all g_partial
            float v = 0.0f;
#pragma unroll
            for (int i = lane; i < NTASK; i += 32) {
                const float w = (i >= 256) ? -2.0f : 1.0f;
                v += w * g_partial[i];
            }
#pragma unroll
            for (int off = 16; off > 0; off >>= 1)
                v += __shfl_down_sync(0xffffffffu, v, off);
            if (lane == 0) {
                g_done = 0;                          // reset for next replay
                out[0] = v * (1.0f / (float)A_BATCH);
            }
        }
    } else {
        // ======================= PRODUCER (warps 0..2) =======================
        const int p = q;                             // stream 0..2

        // dX for rows 8*lane .. 8*lane+7 in registers (f32x2 packed)
        u64 dxp[8][8];
#pragma unroll
        for (int r = 0; r < 8; r++) {
            const int i = 8 * lane + r;
            if (i < MM) {
                const float4* pa = reinterpret_cast<const float4*>(rowsrc + i * D_DIM);
                const float4* pb = reinterpret_cast<const float4*>(rowsrc + (i + 1) * D_DIM);
#pragma unroll
                for (int k = 0; k < 4; k++) {
                    float4 va = pa[k], vb = pb[k];
                    dxp[r][2 * k]     = pack2(vb.x - va.x, vb.y - va.y);
                    dxp[r][2 * k + 1] = pack2(vb.z - va.z, vb.w - va.w);
                }
            } else {                                  // row 255 -> (c1,c2)=(1,1)
#pragma unroll
                for (int k = 0; k < 8; k++) dxp[r][k] = 0ull;
            }
        }

        const u64 ONE2   = pack2(1.0f, 1.0f);
        const u64 HALF2  = pack2(0.5f, 0.5f);
        const u64 K112   = pack2( 0.0833333333333333f,  0.0833333333333333f);
        const u64 MK112  = pack2(-0.0833333333333333f, -0.0833333333333333f);

        int cons_c = -1;
        const u32 cons_a = flags_b + 12;
        const u32 done_a = flags_b + 4u * (u32)p;
        u32 colb = ring_b + (u32)p * SLOT_B + 80u * (u32)lane;
        const u32 colb_lim = ring_b + (u32)(RB * SLOT_B) + 80u * (u32)lane;
        const ulonglong2* dyp =
            reinterpret_cast<const ulonglong2*>(s_dY + p * D_DIM);

        auto produce = [&](ulonglong2 y0, ulonglong2 y1,
                           ulonglong2 y2, ulonglong2 y3) {
#pragma unroll
            for (int h = 0; h < 4; h++) {             // row pairs (2h, 2h+1)
                u64 acc_a = mul2(dxp[2 * h][0], y0.x);
                acc_a = fma2(dxp[2 * h][1], y0.y, acc_a);
                acc_a = fma2(dxp[2 * h][2], y1.x, acc_a);
                acc_a = fma2(dxp[2 * h][3], y1.y, acc_a);
                acc_a = fma2(dxp[2 * h][4], y2.x, acc_a);
                acc_a = fma2(dxp[2 * h][5], y2.y, acc_a);
                acc_a = fma2(dxp[2 * h][6], y3.x, acc_a);
                acc_a = fma2(dxp[2 * h][7], y3.y, acc_a);
                u64 acc_b = mul2(dxp[2 * h + 1][0], y0.x);
                acc_b = fma2(dxp[2 * h + 1][1], y0.y, acc_b);
                acc_b = fma2(dxp[2 * h + 1][2], y1.x, acc_b);
                acc_b = fma2(dxp[2 * h + 1][3], y1.y, acc_b);
                acc_b = fma2(dxp[2 * h + 1][4], y2.x, acc_b);
                acc_b = fma2(dxp[2 * h + 1][5], y2.y, acc_b);
                acc_b = fma2(dxp[2 * h + 1][6], y3.x, acc_b);
                acc_b = fma2(dxp[2 * h + 1][7], y3.y, acc_b);
                float lo_a, hi_a, lo_b, hi_b;
                unpack2(acc_a, lo_a, hi_a);
                unpack2(acc_b, lo_b, hi_b);
                const u64 g2 = pack2(lo_a + hi_a, lo_b + hi_b); // (g_a, g_b)
                const u64 h2 = mul2(g2, g2);
                const u64 u2 = fma2(h2, K112, ONE2);
                const u64 c1p = fma2(g2, HALF2, u2);   // (c1_a, c1_b)
                const u64 c2p = fma2(h2, MK112, ONE2); // (c2_a, c2_b)
                float c1a, c1b, c2a, c2b;
                unpack2(c1p, c1a, c1b);
                unpack2(c2p, c2a, c2b);
                sts128(colb + 16 * h, c1a, c2a, c1b, c2b);
            }
            dyp += 3 * 4;                             // advance 3 columns
            colb += 3 * SLOT_B;
            if (colb >= colb_lim) colb -= (u32)(RB * SLOT_B);
        };

        int c = p;
#pragma unroll 1
        for (; c < RB; c += 3) {                      // no ring wait needed
            produce(dyp[0], dyp[1], dyp[2], dyp[3]);
            sts_rel(done_a, c);                       // branchless publish
        }
#pragma unroll 1
        for (; c < MM; c += 3) {                      // slot reuse: wait c-7
            // prefetch dY column before the spin (no ring dependence)
            const ulonglong2 y0 = dyp[0], y1 = dyp[1], y2 = dyp[2], y3 = dyp[3];
            const int need = c - 7;
            while (cons_c < need) cons_c = lds_acq(cons_a);   // bare spin
            produce(y0, y1, y2, y3);
            sts_rel(done_a, c);                       // branchless publish
        }
    }
}

extern "C" void kernel_launch(void* const* d_in, const int* in_sizes, int n_in,
                              void* d_out, int out_size)
{
    const float* X = (const float*)d_in[0];
    const float* Y = (const float*)d_in[1];
    float* out = (float*)d_out;

    cudaFuncSetAttribute(sig_pde_kernel,
                         cudaFuncAttributeMaxDynamicSharedMemorySize, SMEM_BYTES);

    sig_pde_kernel<<<NTASK, 128, SMEM_BYTES>>>(X, Y, out);
}

// round 14
// speedup vs baseline: 1.3761x; 1.3761x over previous
#include <cuda_runtime.h>
#include <cstdint>

// Problem constants
#define A_BATCH 128
#define M_LEN   256
#define D_DIM   16
#define MM      255            // PDE grid size (M-1)
#define NTASK   384            // 3 PDE solves x 128 batch

// Ring geometry: one slot per column of raw g values (1 float per cell).
// Lane region = 12 words (8 data + 4 pad): quad stride 3 is coprime to 32
// -> conflict-free LDS.128/STS.128. SLOT_W % 32 == 0 -> slot-independent
// banks. RB=60 -> producer run-ahead = RB-31 = 29 columns (decoupling);
// gate: cons >= c-29. Consumer publish lag <=3 -> deadlock-free.
#define RB      60
#define SLOT_W  384            // 12 words * 32 lanes
#define SLOT_B  (SLOT_W * 4)   // 1536 bytes
#define RING_W  (RB * SLOT_W)  // 23040 words
#define DY_W    (MM * D_DIM)   // 4080 words
#define FLAGS_OFF (RING_W + DY_W)
#define TEAM_W  (FLAGS_OFF + 8)
#define SMEM_BYTES (TEAM_W * 4)   // 108,512 B -> 2 CTAs/SM co-resident

#define K12 0.0833333333333333f

typedef unsigned long long u64;
typedef unsigned int u32;

__device__ float g_partial[NTASK];
__device__ int   g_done = 0;       // last-CTA counter (reset by the last CTA)

__device__ __forceinline__ u64 pack2(float lo, float hi) {
    u64 r; asm("mov.b64 %0,{%1,%2};" : "=l"(r) : "f"(lo), "f"(hi)); return r;
}
__device__ __forceinline__ void unpack2(u64 v, float& lo, float& hi) {
    asm("mov.b64 {%0,%1},%2;" : "=f"(lo), "=f"(hi) : "l"(v));
}
__device__ __forceinline__ u64 fma2(u64 a, u64 b, u64 c) {
    u64 d; asm("fma.rn.f32x2 %0,%1,%2,%3;" : "=l"(d) : "l"(a), "l"(b), "l"(c)); return d;
}
__device__ __forceinline__ u64 mul2(u64 a, u64 b) {
    u64 d; asm("mul.rn.f32x2 %0,%1,%2;" : "=l"(d) : "l"(a), "l"(b)); return d;
}
__device__ __forceinline__ int lds_acq(u32 a) {
    int v; asm volatile("ld.acquire.cta.shared.b32 %0,[%1];" : "=r"(v) : "r"(a)); return v;
}
__device__ __forceinline__ void sts_rel(u32 a, int v) {
    asm volatile("st.release.cta.shared.b32 [%0],%1;" :: "r"(a), "r"(v));
}
__device__ __forceinline__ void lds128(u32 a, float& x, float& y, float& z, float& w) {
    asm volatile("ld.shared.v4.f32 {%0,%1,%2,%3},[%4];"
                 : "=f"(x), "=f"(y), "=f"(z), "=f"(w) : "r"(a));
}
__device__ __forceinline__ void sts128(u32 a, float x, float y, float z, float w) {
    asm volatile("st.shared.v4.f32 [%0],{%1,%2,%3,%4};"
                 :: "r"(a), "f"(x), "f"(y), "f"(z), "f"(w));
}

// One CTA = one task = 128 threads. Consumer = warp 3; producers = warps
// 0..2 (warp p owns columns ≡ p mod 3; lane computes rows 8l..8l+7 from
// register dX and stores raw g). Consumer reconstructs (c1,c2) from g with
// the producer's exact FFMA sequence (bitwise-identical results). R12
// protocol byte-for-byte: per-step cached waits, lane-0 publishes.
__global__ void __launch_bounds__(128, 2) sig_pde_kernel(
    const float* __restrict__ X, const float* __restrict__ Y,
    float* __restrict__ out)
{
    extern __shared__ float smem[];
    u32 sb;
    asm("{.reg .u64 t; cvta.to.shared.u64 t,%1; cvt.u32.u64 %0,t;}"
        : "=r"(sb) : "l"(smem));

    const int t    = threadIdx.x;
    const int q    = t >> 5;           // warp 0..3
    const int lane = t & 31;

    const int task = (int)blockIdx.x;
    const int pde  = task >> 7;        // 0:(X,X) 1:(Y,Y) 2:(X,Y)
    const int a    = task & 127;
    const float* rowsrc = (pde == 1 ? Y : X) + (size_t)a * (M_LEN * D_DIM);
    const float* colsrc = (pde == 0 ? X : Y) + (size_t)a * (M_LEN * D_DIM);

    float* s_dY = smem + RING_W;
    const u32 ring_b  = sb;
    const u32 flags_b = sb + FLAGS_OFF * 4;

    // dY[j][k] = colsrc[j+1][k] - colsrc[j][k]
    for (int idx = t; idx < DY_W; idx += 128)
        s_dY[idx] = colsrc[idx + D_DIM] - colsrc[idx];
    if (t < 4) ((volatile int*)(smem + FLAGS_OFF))[t] = -1; // done0..2, cons
    __syncthreads();   // the ONLY cta barrier

    if (q == 3) {
        // ======================= CONSUMER (warp 3) =======================
        float L[8];
#pragma unroll
        for (int r = 0; r < 8; r++) L[r] = 1.0f;     // K[row+1][0] = 1
        float nb_prev = 1.0f, last = 0.0f;
        u32 ad = ring_b + 48u * (u32)lane;
        const u32 ad_lim = ad + (u32)(RB * SLOT_B);
        const u32 cons_a = flags_b + 12;
        const u32 fa0 = flags_b, fa1 = flags_b + 4, fa2 = flags_b + 8;
        int f0 = -1, f1 = -1, f2 = -1;

        auto waitf = [&](int& f, u32 fa, int s) {
            if (f < s) { do { f = lds_acq(fa); } while (f < s); }
        };
        auto loadR = [&](float* G) {                 // load g col at ad, advance
            lds128(ad,      G[0], G[1], G[2], G[3]);
            lds128(ad + 16, G[4], G[5], G[6], G[7]);
            ad += SLOT_B;
            if (ad >= ad_lim) ad -= (u32)(RB * SLOT_B);
        };
        auto chain = [&](const float* G, float nb_new) {
            // reconstruct coefficients (producer's exact op sequence)
            float c1[8], c2[8];
#pragma unroll
            for (int r = 0; r < 8; r++) {
                const float g = G[r];
                const float h = g * g;
                const float u = fmaf(h,  K12, 1.0f);
                c1[r] = fmaf(g, 0.5f, u);
                c2[r] = fmaf(h, -K12, 1.0f);
            }
            const float up0 = (lane == 0) ? 1.0f : nb_new;
            const float dg0 = (lane == 0) ? 1.0f : nb_prev;
            float P0 = fmaf(L[0], c1[0], -(dg0  * c2[0]));
            float P1 = fmaf(L[1], c1[1], -(L[0] * c2[1]));
            float P2 = fmaf(L[2], c1[2], -(L[1] * c2[2]));
            float P3 = fmaf(L[3], c1[3], -(L[2] * c2[3]));
            float P4 = fmaf(L[4], c1[4], -(L[3] * c2[4]));
            float P5 = fmaf(L[5], c1[5], -(L[4] * c2[5]));
            float P6 = fmaf(L[6], c1[6], -(L[5] * c2[6]));
            float P7 = fmaf(L[7], c1[7], -(L[6] * c2[7]));
            float k = fmaf(up0, c1[0], P0); L[0] = k;
            k = fmaf(k, c1[1], P1); L[1] = k;
            k = fmaf(k, c1[2], P2); L[2] = k;
            k = fmaf(k, c1[3], P3); L[3] = k;
            k = fmaf(k, c1[4], P4); L[4] = k;
            k = fmaf(k, c1[5], P5); L[5] = k;
            k = fmaf(k, c1[6], P6); L[6] = k;
            k = fmaf(k, c1[7], P7); L[7] = k;
            last = k;
            nb_prev = nb_new;
        };
        auto body_ld = [&](float nb_new) {           // direct load + chain
            float G[8];
            loadR(G);
            chain(G, nb_new);
        };

        // ---- ramp: s = 0..32 (lane predicates + flag checks) ----
#pragma unroll 1
        for (int s = 0; s < 33; s += 3) {
            { float nb = __shfl_up_sync(0xffffffffu, last, 1);
              waitf(f0, fa0, s);     if (lane <= s)     body_ld(nb); }
            { float nb = __shfl_up_sync(0xffffffffu, last, 1);
              waitf(f1, fa1, s + 1); if (lane <= s + 1) body_ld(nb); }
            { float nb = __shfl_up_sync(0xffffffffu, last, 1);
              waitf(f2, fa2, s + 2); if (lane <= s + 2) body_ld(nb); }
            if (lane == 0) sts_rel(cons_a, s + 2);
        }

        // ---- steady (pipelined): steps 33..248 in 6-step groups ----
        float R[8], T[8];
        waitf(f0, fa0, 33);
        loadR(R);                                    // data for step 33
#pragma unroll 1
        for (int s = 33; s < 249; s += 6) {
            { float nb = __shfl_up_sync(0xffffffffu, last, 1);
              waitf(f1, fa1, s + 1); loadR(T); chain(R, nb); }
            { float nb = __shfl_up_sync(0xffffffffu, last, 1);
              waitf(f2, fa2, s + 2); loadR(R); chain(T, nb); }
            { float nb = __shfl_up_sync(0xffffffffu, last, 1);
              waitf(f0, fa0, s + 3); loadR(T); chain(R, nb); }
            if (lane == 0) sts_rel(cons_a, s + 2);
            { float nb = __shfl_up_sync(0xffffffffu, last, 1);
              waitf(f1, fa1, s + 4); loadR(R); chain(T, nb); }
            { float nb = __shfl_up_sync(0xffffffffu, last, 1);
              waitf(f2, fa2, s + 5); loadR(T); chain(R, nb); }
            { float nb = __shfl_up_sync(0xffffffffu, last, 1);
              waitf(f0, fa0, s + 6); loadR(R); chain(T, nb); }
            if (lane == 0) sts_rel(cons_a, s + 5);
        }
        // ---- peel: steps 249..254 (last wait clamped; junk preload ok) ----
        { float nb = __shfl_up_sync(0xffffffffu, last, 1);
          waitf(f1, fa1, 250); loadR(T); chain(R, nb); }       // 249
        { float nb = __shfl_up_sync(0xffffffffu, last, 1);
          waitf(f2, fa2, 251); loadR(R); chain(T, nb); }       // 250
        { float nb = __shfl_up_sync(0xffffffffu, last, 1);
          waitf(f0, fa0, 252); loadR(T); chain(R, nb); }       // 251
        if (lane == 0) sts_rel(cons_a, 251);
        { float nb = __shfl_up_sync(0xffffffffu, last, 1);
          waitf(f1, fa1, 253); loadR(R); chain(T, nb); }       // 252
        { float nb = __shfl_up_sync(0xffffffffu, last, 1);
          waitf(f2, fa2, 254); loadR(T); chain(R, nb); }       // 253
        { float nb = __shfl_up_sync(0xffffffffu, last, 1);
          loadR(R); chain(T, nb); }                            // 254 (junk preload)
        if (lane == 0) sts_rel(cons_a, 254);
        // rewind the junk preload so tail's direct loads hit the right column
        ad += (u32)(RB * SLOT_B) - SLOT_B;
        if (ad >= ad_lim) ad -= (u32)(RB * SLOT_B);

        // ---- tail: s = 255..285, flag-free (all cols <=254 already waited) --
#pragma unroll 1
        for (int s = 255; s < 286; s++) {
            float nb = __shfl_up_sync(0xffffffffu, last, 1);
            if (lane >= s - 254) body_ld(nb);
        }
        // K[255][255] = L[6] of lane 31 (global row 254)
        if (lane == 31) g_partial[task] = L[6];

        // ---- fused reduction: last CTA sums all partials ----
        int old = 0;
        if (lane == 31) {
            __threadfence();                         // g_partial visible
            old = atomicAdd(&g_done, 1);
        }
        old = __shfl_sync(0xffffffffu, old, 31);
        if (old == NTASK - 1) {
            __threadfence();                         // see all g_partial
            float v = 0.0f;
#pragma unroll
            for (int i = lane; i < NTASK; i += 32) {
                const float w = (i >= 256) ? -2.0f : 1.0f;
                v += w * g_partial[i];
            }
#pragma unroll
            for (int off = 16; off > 0; off >>= 1)
                v += __shfl_down_sync(0xffffffffu, v, off);
            if (lane == 0) {
                g_done = 0;                          // reset for next replay
                out[0] = v * (1.0f / (float)A_BATCH);
            }
        }
    } else {
        // ======================= PRODUCER (warps 0..2) =======================
        const int p = q;                             // stream 0..2

        // dX for rows 8*lane .. 8*lane+7 in registers (f32x2 packed)
        u64 dxp[8][8];
#pragma unroll
        for (int r = 0; r < 8; r++) {
            const int i = 8 * lane + r;
            if (i < MM) {
                const float4* pa = reinterpret_cast<const float4*>(rowsrc + i * D_DIM);
                const float4* pb = reinterpret_cast<const float4*>(rowsrc + (i + 1) * D_DIM);
#pragma unroll
                for (int k = 0; k < 4; k++) {
                    float4 va = pa[k], vb = pb[k];
                    dxp[r][2 * k]     = pack2(vb.x - va.x, vb.y - va.y);
                    dxp[r][2 * k + 1] = pack2(vb.z - va.z, vb.w - va.w);
                }
            } else {                                  // row 255 -> g = 0
#pragma unroll
                for (int k = 0; k < 8; k++) dxp[r][k] = 0ull;
            }
        }

        int cons_c = -1;
        const u32 cons_a = flags_b + 12;
        const u32 done_a = flags_b + 4u * (u32)p;
        u32 colb = ring_b + (u32)p * SLOT_B + 48u * (u32)lane;
        const u32 colb_lim = ring_b + (u32)(RB * SLOT_B) + 48u * (u32)lane;
        const ulonglong2* dyp =
            reinterpret_cast<const ulonglong2*>(s_dY + p * D_DIM);

        auto produce = [&](ulonglong2 y0, ulonglong2 y1,
                           ulonglong2 y2, ulonglong2 y3) {
            float gv[8];
#pragma unroll
            for (int h = 0; h < 4; h++) {             // row pairs (2h, 2h+1)
                u64 acc_a = mul2(dxp[2 * h][0], y0.x);
                acc_a = fma2(dxp[2 * h][1], y0.y, acc_a);
                acc_a = fma2(dxp[2 * h][2], y1.x, acc_a);
                acc_a = fma2(dxp[2 * h][3], y1.y, acc_a);
                acc_a = fma2(dxp[2 * h][4], y2.x, acc_a);
                acc_a = fma2(dxp[2 * h][5], y2.y, acc_a);
                acc_a = fma2(dxp[2 * h][6], y3.x, acc_a);
                acc_a = fma2(dxp[2 * h][7], y3.y, acc_a);
                u64 acc_b = mul2(dxp[2 * h + 1][0], y0.x);
                acc_b = fma2(dxp[2 * h + 1][1], y0.y, acc_b);
                acc_b = fma2(dxp[2 * h + 1][2], y1.x, acc_b);
                acc_b = fma2(dxp[2 * h + 1][3], y1.y, acc_b);
                acc_b = fma2(dxp[2 * h + 1][4], y2.x, acc_b);
                acc_b = fma2(dxp[2 * h + 1][5], y2.y, acc_b);
                acc_b = fma2(dxp[2 * h + 1][6], y3.x, acc_b);
                acc_b = fma2(dxp[2 * h + 1][7], y3.y, acc_b);
                float lo_a, hi_a, lo_b, hi_b;
                unpack2(acc_a, lo_a, hi_a);
                unpack2(acc_b, lo_b, hi_b);
                gv[2 * h]     = lo_a + hi_a;
                gv[2 * h + 1] = lo_b + hi_b;
            }
            sts128(colb,      gv[0], gv[1], gv[2], gv[3]);
            sts128(colb + 16, gv[4], gv[5], gv[6], gv[7]);
            dyp += 3 * 4;                             // advance 3 columns
            colb += 3 * SLOT_B;
            if (colb >= colb_lim) colb -= (u32)(RB * SLOT_B);
        };

        int c = p;
#pragma unroll 1
        for (; c < RB; c += 3) {                      // no ring wait needed
            produce(dyp[0], dyp[1], dyp[2], dyp[3]);
            if (lane == 0) sts_rel(done_a, c);
        }
#pragma unroll 1
        for (; c < MM; c += 3) {                      // slot reuse: wait c-29
            // prefetch dY column before the spin (no ring dependence)
            const ulonglong2 y0 = dyp[0], y1 = dyp[1], y2 = dyp[2], y3 = dyp[3];
            const int need = c - (RB - 31);           // = c - 29
            while (cons_c < need) cons_c = lds_acq(cons_a);   // bare spin
            produce(y0, y1, y2, y3);
            if (lane == 0) sts_rel(done_a, c);
        }
    }
}

extern "C" void kernel_launch(void* const* d_in, const int* in_sizes, int n_in,
                              void* d_out, int out_size)
{
    const float* X = (const float*)d_in[0];
    const float* Y = (const float*)d_in[1];
    float* out = (float*)d_out;

    cudaFuncSetAttribute(sig_pde_kernel,
                         cudaFuncAttributeMaxDynamicSharedMemorySize, SMEM_BYTES);

    sig_pde_kernel<<<NTASK, 128, SMEM_BYTES>>>(X, Y, out);
}